// round 1
// baseline (speedup 1.0000x reference)
#include <cuda_runtime.h>

// Problem constants
#define B_ 16
#define S_ 577
#define E_ 1024
#define H_ 16
#define D_ 64
#define M_ (B_ * S_)          // 9232 rows

// GEMM tiling
#define BM 128
#define BN 128
#define BK 16
#define TM 8
#define TN 8
#define NTHREADS 256
#define PAD 4

// Scratch (static device globals — allocation-free per harness rules)
__device__ float g_V[(size_t)H_ * S_ * B_ * D_]; // [h][s][b][d]  (37.8 MB)
__device__ float g_P[(size_t)H_ * S_ * S_];      // [h][i][j]     (21.3 MB)
__device__ float g_O[(size_t)M_ * E_];           // [b*S+s][e]    (37.8 MB)

// ---------------------------------------------------------------------------
// NT GEMM: C[m,n] = sum_k A[m,k] * W[n,k] + bias[n]
// MODE 0: A = hidden_states, C written into g_V in [h][s][b][d] layout
// MODE 1: A = g_O,           C written to d_out in [m][n] layout
// ---------------------------------------------------------------------------
template <int MODE>
__global__ __launch_bounds__(NTHREADS, 2)
void gemm_nt_kernel(const float* __restrict__ Ain,
                    const float* __restrict__ W,
                    const float* __restrict__ bias,
                    float* __restrict__ Cout)
{
    const float* __restrict__ A = (MODE == 0) ? Ain : g_O;

    __shared__ float As[BK][BM + PAD];
    __shared__ float Bs[BK][BN + PAD];

    const int tid = threadIdx.x;
    const int tm0 = blockIdx.y * BM;
    const int tn0 = blockIdx.x * BN;
    const int ty  = tid >> 4;
    const int tx  = tid & 15;

    float acc[TM][TN];
#pragma unroll
    for (int i = 0; i < TM; i++)
#pragma unroll
        for (int j = 0; j < TN; j++) acc[i][j] = 0.f;

    for (int kt = 0; kt < E_ / BK; kt++) {
        // Load A tile (BM x BK) and W tile (BN x BK), both K-contiguous, float4
#pragma unroll
        for (int p = 0; p < 2; p++) {
            int v   = tid + NTHREADS * p;   // 0..511
            int row = v >> 2;               // 0..127
            int c4  = (v & 3) * 4;          // 0,4,8,12
            int m   = tm0 + row;
            float4 a = make_float4(0.f, 0.f, 0.f, 0.f);
            if (m < M_) a = *(const float4*)&A[(size_t)m * E_ + kt * BK + c4];
            As[c4 + 0][row] = a.x; As[c4 + 1][row] = a.y;
            As[c4 + 2][row] = a.z; As[c4 + 3][row] = a.w;

            int n = tn0 + row;              // N = 1024 exact, no guard needed
            float4 b = *(const float4*)&W[(size_t)n * E_ + kt * BK + c4];
            Bs[c4 + 0][row] = b.x; Bs[c4 + 1][row] = b.y;
            Bs[c4 + 2][row] = b.z; Bs[c4 + 3][row] = b.w;
        }
        __syncthreads();

#pragma unroll
        for (int k = 0; k < BK; k++) {
            float a[TM], b[TN];
            *(float4*)&a[0] = *(const float4*)&As[k][ty * TM];
            *(float4*)&a[4] = *(const float4*)&As[k][ty * TM + 4];
            *(float4*)&b[0] = *(const float4*)&Bs[k][tx * TN];
            *(float4*)&b[4] = *(const float4*)&Bs[k][tx * TN + 4];
#pragma unroll
            for (int i = 0; i < TM; i++)
#pragma unroll
                for (int j = 0; j < TN; j++)
                    acc[i][j] = fmaf(a[i], b[j], acc[i][j]);
        }
        __syncthreads();
    }

    const int n0 = tn0 + tx * TN;
    if (MODE == 0) {
        // n = h*64 + d; tx*TN is a multiple of 8, so the 8 j's stay in one head
        const int h  = n0 / D_;
        const int d0 = n0 % D_;
#pragma unroll
        for (int i = 0; i < TM; i++) {
            int m = tm0 + ty * TM + i;
            if (m < M_) {
                int bb = m / S_;
                int s  = m - bb * S_;
                float* dst = &g_V[(((size_t)h * S_ + s) * B_ + bb) * D_ + d0];
#pragma unroll
                for (int j = 0; j < TN; j++)
                    dst[j] = acc[i][j] + bias[n0 + j];
            }
        }
    } else {
#pragma unroll
        for (int i = 0; i < TM; i++) {
            int m = tm0 + ty * TM + i;
            if (m < M_) {
#pragma unroll
                for (int j = 0; j < TN; j++)
                    Cout[(size_t)m * E_ + n0 + j] = acc[i][j] + bias[n0 + j];
            }
        }
    }
}

// ---------------------------------------------------------------------------
// Row softmax of share_bias -> g_P.   attn = softmax(bias) (Q path cancels).
// One block (256 threads) per (h,i) row of length 577.
// ---------------------------------------------------------------------------
__global__ __launch_bounds__(256)
void softmax_kernel(const float* __restrict__ bias)
{
    const int row = blockIdx.x;                 // 0 .. H_*S_-1
    const float* __restrict__ src = bias + (size_t)row * S_;
    float* __restrict__ dst = g_P + (size_t)row * S_;
    const int tid = threadIdx.x;

    __shared__ float shm[8];
    __shared__ float shs[8];

    float v0 = (tid       < S_) ? src[tid]       : -3.0e38f;
    float v1 = (tid + 256 < S_) ? src[tid + 256] : -3.0e38f;
    float v2 = (tid + 512 < S_) ? src[tid + 512] : -3.0e38f;

    float mx = fmaxf(v0, fmaxf(v1, v2));
#pragma unroll
    for (int o = 16; o > 0; o >>= 1)
        mx = fmaxf(mx, __shfl_xor_sync(0xffffffffu, mx, o));
    if ((tid & 31) == 0) shm[tid >> 5] = mx;
    __syncthreads();
    mx = shm[0];
#pragma unroll
    for (int w = 1; w < 8; w++) mx = fmaxf(mx, shm[w]);

    float e0 = __expf(v0 - mx);
    float e1 = __expf(v1 - mx);
    float e2 = __expf(v2 - mx);
    float s = e0 + e1 + e2;
#pragma unroll
    for (int o = 16; o > 0; o >>= 1)
        s += __shfl_xor_sync(0xffffffffu, s, o);
    if ((tid & 31) == 0) shs[tid >> 5] = s;
    __syncthreads();
    s = shs[0];
#pragma unroll
    for (int w = 1; w < 8; w++) s += shs[w];

    const float inv = 1.0f / s;
    if (tid       < S_) dst[tid]       = e0 * inv;
    if (tid + 256 < S_) dst[tid + 256] = e1 * inv;
    if (tid + 512 < S_) dst[tid + 512] = e2 * inv;
}

// ---------------------------------------------------------------------------
// Per-head NN GEMM: O_h[i, (b,d)] = sum_j P[h][i,j] * V[h][j][(b,d)]
// P batch-invariant -> batches folded into N (N = B*D = 1024).
// Output written to g_O in [b*S+i][h*64+d] layout (row-major for final GEMM).
// ---------------------------------------------------------------------------
__global__ __launch_bounds__(NTHREADS, 2)
void gemm_pv_kernel()
{
    const int h = blockIdx.z;
    const float* __restrict__ P  = g_P + (size_t)h * S_ * S_;
    const float* __restrict__ Vp = g_V + (size_t)h * S_ * (B_ * D_);

    __shared__ float As[BK][BM + PAD];
    __shared__ float Bs[BK][BN + PAD];

    const int tid = threadIdx.x;
    const int tm0 = blockIdx.y * BM;
    const int tn0 = blockIdx.x * BN;
    const int ty  = tid >> 4;
    const int tx  = tid & 15;

    float acc[TM][TN];
#pragma unroll
    for (int i = 0; i < TM; i++)
#pragma unroll
        for (int j = 0; j < TN; j++) acc[i][j] = 0.f;

    const int NKT = (S_ + BK - 1) / BK;  // 37 (K=577 has a 1-wide tail)
    for (int kt = 0; kt < NKT; kt++) {
        const int k0 = kt * BK;
        // A tile: P rows (row stride 577 — scalar, K-coalesced loads)
#pragma unroll
        for (int p = 0; p < 8; p++) {
            int v   = tid + NTHREADS * p;  // 0..2047
            int row = v >> 4;
            int kk  = v & 15;
            int m = tm0 + row, k = k0 + kk;
            As[kk][row] = (m < S_ && k < S_) ? P[(size_t)m * S_ + k] : 0.f;
        }
        // B tile: Vp is [K=577][N=1024] row-major, N-contiguous float4
#pragma unroll
        for (int p = 0; p < 2; p++) {
            int v  = tid + NTHREADS * p;   // 0..511
            int kk = v >> 5;               // 0..15
            int n4 = (v & 31) * 4;         // 0..124
            int k = k0 + kk;
            float4 b = make_float4(0.f, 0.f, 0.f, 0.f);
            if (k < S_) b = *(const float4*)&Vp[(size_t)k * (B_ * D_) + tn0 + n4];
            *(float4*)&Bs[kk][n4] = b;
        }
        __syncthreads();

#pragma unroll
        for (int k = 0; k < BK; k++) {
            float a[TM], b[TN];
            *(float4*)&a[0] = *(const float4*)&As[k][ty * TM];
            *(float4*)&a[4] = *(const float4*)&As[k][ty * TM + 4];
            *(float4*)&b[0] = *(const float4*)&Bs[k][tx * TN];
            *(float4*)&b[4] = *(const float4*)&Bs[k][tx * TN + 4];
#pragma unroll
            for (int i = 0; i < TM; i++)
#pragma unroll
                for (int j = 0; j < TN; j++)
                    acc[i][j] = fmaf(a[i], b[j], acc[i][j]);
        }
        __syncthreads();
    }

    // n = b*64 + d  (tx*TN multiple of 8 -> 8 j's stay within one batch b)
    const int n0 = tn0 + tx * TN;
    const int bb = n0 / D_;
    const int d0 = n0 % D_;
#pragma unroll
    for (int i = 0; i < TM; i++) {
        int m = tm0 + ty * TM + i;
        if (m < S_) {
            float* dst = &g_O[((size_t)bb * S_ + m) * E_ + h * D_ + d0];
#pragma unroll
            for (int j = 0; j < TN; j++)
                dst[j] = acc[i][j];
        }
    }
}

// ---------------------------------------------------------------------------
// Launch: V-proj GEMM -> softmax(P) -> per-head P@V -> out-proj GEMM
// Q projection / share_key are dead code (softmax shift-invariance).
// ---------------------------------------------------------------------------
extern "C" void kernel_launch(void* const* d_in, const int* in_sizes, int n_in,
                              void* d_out, int out_size)
{
    const float* hidden = (const float*)d_in[0];
    // d_in[1] q_w, d_in[2] q_b, d_in[7] share_key, d_in[9] layer: unused (cancel)
    const float* v_w    = (const float*)d_in[3];
    const float* v_b    = (const float*)d_in[4];
    const float* out_w  = (const float*)d_in[5];
    const float* out_b  = (const float*)d_in[6];
    const float* s_bias = (const float*)d_in[8];
    float* out = (float*)d_out;

    dim3 g_big(E_ / BN, (M_ + BM - 1) / BM);            // 8 x 73
    dim3 g_pv(E_ / BN, (S_ + BM - 1) / BM, H_);         // 8 x 5 x 16

    gemm_nt_kernel<0><<<g_big, NTHREADS>>>(hidden, v_w, v_b, nullptr);
    softmax_kernel<<<H_ * S_, 256>>>(s_bias);
    gemm_pv_kernel<<<g_pv, NTHREADS>>>();
    gemm_nt_kernel<1><<<g_big, NTHREADS>>>(nullptr, out_w, out_b, out);
}

// round 2
// speedup vs baseline: 1.5842x; 1.5842x over previous
#include <cuda_runtime.h>

// Problem constants
#define B_ 16
#define S_ 577
#define E_ 1024
#define H_ 16
#define D_ 64
#define M_ (B_ * S_)          // 9232 rows

// GEMM tiling
#define BM 128
#define BN 128
#define BK 16
#define TM 8
#define TN 8
#define NTHREADS 256
#define PAD 4

// Scratch (static device globals — allocation-free per harness rules)
__device__ float g_V[(size_t)H_ * S_ * B_ * D_]; // [h][s][b][d]
__device__ float g_P[(size_t)H_ * S_ * S_];      // [h][i][j]
__device__ float g_O[(size_t)M_ * E_];           // [b*S+s][e]

// Packed f32x2 FMA (sm_103a FFMA2 — only reachable via PTX fma.rn.f32x2)
union F2U { float2 f; unsigned long long u; };
__device__ __forceinline__ float2 ffma2(float2 a, float2 b, float2 c) {
    F2U A, Bu, C, D;
    A.f = a; Bu.f = b; C.f = c;
    asm("fma.rn.f32x2 %0, %1, %2, %3;"
        : "=l"(D.u) : "l"(A.u), "l"(Bu.u), "l"(C.u));
    return D.f;
}

// ---------------------------------------------------------------------------
// NT GEMM: C[m,n] = sum_k A[m,k] * W[n,k] + bias[n]
// MODE 0: A = hidden_states, C -> g_V in [h][s][b][d] layout
// MODE 1: A = g_O,           C -> d_out [m][n]
// ---------------------------------------------------------------------------
template <int MODE>
__global__ __launch_bounds__(NTHREADS, 2)
void gemm_nt_kernel(const float* __restrict__ Ain,
                    const float* __restrict__ W,
                    const float* __restrict__ bias,
                    float* __restrict__ Cout)
{
    const float* __restrict__ A = (MODE == 0) ? Ain : g_O;

    __shared__ float As[BK][BM + PAD];
    __shared__ float Bs[BK][BN + PAD];

    const int tid = threadIdx.x;
    const int tm0 = blockIdx.y * BM;
    const int tn0 = blockIdx.x * BN;
    const int ty  = tid >> 4;
    const int tx  = tid & 15;

    float2 acc2[TM][TN / 2];
#pragma unroll
    for (int i = 0; i < TM; i++)
#pragma unroll
        for (int j = 0; j < TN / 2; j++) acc2[i][j] = make_float2(0.f, 0.f);

    // Register prefetch buffers (double-buffer HBM loads against compute)
    float4 ra[2], rb[2];
#pragma unroll
    for (int p = 0; p < 2; p++) {
        int v = tid + NTHREADS * p, row = v >> 2, c4 = (v & 3) * 4;
        int m = tm0 + row;
        ra[p] = make_float4(0.f, 0.f, 0.f, 0.f);
        if (m < M_) ra[p] = *(const float4*)&A[(size_t)m * E_ + c4];
        rb[p] = *(const float4*)&W[(size_t)(tn0 + row) * E_ + c4];
    }

    const int NT = E_ / BK;
    for (int kt = 0; kt < NT; kt++) {
        // Commit prefetched tile to SMEM
#pragma unroll
        for (int p = 0; p < 2; p++) {
            int v = tid + NTHREADS * p, row = v >> 2, c4 = (v & 3) * 4;
            As[c4 + 0][row] = ra[p].x; As[c4 + 1][row] = ra[p].y;
            As[c4 + 2][row] = ra[p].z; As[c4 + 3][row] = ra[p].w;
            Bs[c4 + 0][row] = rb[p].x; Bs[c4 + 1][row] = rb[p].y;
            Bs[c4 + 2][row] = rb[p].z; Bs[c4 + 3][row] = rb[p].w;
        }
        __syncthreads();

        // Issue next tile's global loads before compute
        if (kt + 1 < NT) {
            int koff = (kt + 1) * BK;
#pragma unroll
            for (int p = 0; p < 2; p++) {
                int v = tid + NTHREADS * p, row = v >> 2, c4 = (v & 3) * 4;
                int m = tm0 + row;
                ra[p] = make_float4(0.f, 0.f, 0.f, 0.f);
                if (m < M_) ra[p] = *(const float4*)&A[(size_t)m * E_ + koff + c4];
                rb[p] = *(const float4*)&W[(size_t)(tn0 + row) * E_ + koff + c4];
            }
        }

#pragma unroll
        for (int k = 0; k < BK; k++) {
            float a[TM];
            *(float4*)&a[0] = *(const float4*)&As[k][ty * TM];
            *(float4*)&a[4] = *(const float4*)&As[k][ty * TM + 4];
            float4 t0 = *(const float4*)&Bs[k][tx * TN];
            float4 t1 = *(const float4*)&Bs[k][tx * TN + 4];
            float2 bb[4] = { make_float2(t0.x, t0.y), make_float2(t0.z, t0.w),
                             make_float2(t1.x, t1.y), make_float2(t1.z, t1.w) };
#pragma unroll
            for (int i = 0; i < TM; i++) {
                float2 a2 = make_float2(a[i], a[i]);
#pragma unroll
                for (int j = 0; j < TN / 2; j++)
                    acc2[i][j] = ffma2(a2, bb[j], acc2[i][j]);
            }
        }
        __syncthreads();
    }

    const int n0 = tn0 + tx * TN;
    float bv[TN];
#pragma unroll
    for (int j = 0; j < TN; j++) bv[j] = bias[n0 + j];

    if (MODE == 0) {
        const int h  = n0 / D_;
        const int d0 = n0 % D_;
#pragma unroll
        for (int i = 0; i < TM; i++) {
            int m = tm0 + ty * TM + i;
            if (m < M_) {
                int bb_ = m / S_;
                int s   = m - bb_ * S_;
                float* dst = &g_V[(((size_t)h * S_ + s) * B_ + bb_) * D_ + d0];
                float4 o0 = make_float4(acc2[i][0].x + bv[0], acc2[i][0].y + bv[1],
                                        acc2[i][1].x + bv[2], acc2[i][1].y + bv[3]);
                float4 o1 = make_float4(acc2[i][2].x + bv[4], acc2[i][2].y + bv[5],
                                        acc2[i][3].x + bv[6], acc2[i][3].y + bv[7]);
                *(float4*)&dst[0] = o0;
                *(float4*)&dst[4] = o1;
            }
        }
    } else {
#pragma unroll
        for (int i = 0; i < TM; i++) {
            int m = tm0 + ty * TM + i;
            if (m < M_) {
                float* dst = &Cout[(size_t)m * E_ + n0];
                float4 o0 = make_float4(acc2[i][0].x + bv[0], acc2[i][0].y + bv[1],
                                        acc2[i][1].x + bv[2], acc2[i][1].y + bv[3]);
                float4 o1 = make_float4(acc2[i][2].x + bv[4], acc2[i][2].y + bv[5],
                                        acc2[i][3].x + bv[6], acc2[i][3].y + bv[7]);
                *(float4*)&dst[0] = o0;
                *(float4*)&dst[4] = o1;
            }
        }
    }
}

// ---------------------------------------------------------------------------
// Row softmax of share_bias -> g_P (Q path cancels under softmax shift-inv.)
// ---------------------------------------------------------------------------
__global__ __launch_bounds__(256)
void softmax_kernel(const float* __restrict__ bias)
{
    const int row = blockIdx.x;
    const float* __restrict__ src = bias + (size_t)row * S_;
    float* __restrict__ dst = g_P + (size_t)row * S_;
    const int tid = threadIdx.x;

    __shared__ float shm[8];
    __shared__ float shs[8];

    float v0 = (tid       < S_) ? src[tid]       : -3.0e38f;
    float v1 = (tid + 256 < S_) ? src[tid + 256] : -3.0e38f;
    float v2 = (tid + 512 < S_) ? src[tid + 512] : -3.0e38f;

    float mx = fmaxf(v0, fmaxf(v1, v2));
#pragma unroll
    for (int o = 16; o > 0; o >>= 1)
        mx = fmaxf(mx, __shfl_xor_sync(0xffffffffu, mx, o));
    if ((tid & 31) == 0) shm[tid >> 5] = mx;
    __syncthreads();
    mx = shm[0];
#pragma unroll
    for (int w = 1; w < 8; w++) mx = fmaxf(mx, shm[w]);

    float e0 = __expf(v0 - mx);
    float e1 = __expf(v1 - mx);
    float e2 = __expf(v2 - mx);
    float s = e0 + e1 + e2;
#pragma unroll
    for (int o = 16; o > 0; o >>= 1)
        s += __shfl_xor_sync(0xffffffffu, s, o);
    if ((tid & 31) == 0) shs[tid >> 5] = s;
    __syncthreads();
    s = shs[0];
#pragma unroll
    for (int w = 1; w < 8; w++) s += shs[w];

    const float inv = 1.0f / s;
    if (tid       < S_) dst[tid]       = e0 * inv;
    if (tid + 256 < S_) dst[tid + 256] = e1 * inv;
    if (tid + 512 < S_) dst[tid + 512] = e2 * inv;
}

// ---------------------------------------------------------------------------
// Per-head NN GEMM: O_h[i,(b,d)] = sum_j P[h][i,j] * V[h][j][(b,d)]
// ---------------------------------------------------------------------------
__global__ __launch_bounds__(NTHREADS, 2)
void gemm_pv_kernel()
{
    const int h = blockIdx.z;
    const float* __restrict__ P  = g_P + (size_t)h * S_ * S_;
    const float* __restrict__ Vp = g_V + (size_t)h * S_ * (B_ * D_);

    __shared__ float As[BK][BM + PAD];
    __shared__ float Bs[BK][BN + PAD];

    const int tid = threadIdx.x;
    const int tm0 = blockIdx.y * BM;
    const int tn0 = blockIdx.x * BN;
    const int ty  = tid >> 4;
    const int tx  = tid & 15;

    float2 acc2[TM][TN / 2];
#pragma unroll
    for (int i = 0; i < TM; i++)
#pragma unroll
        for (int j = 0; j < TN / 2; j++) acc2[i][j] = make_float2(0.f, 0.f);

    float  raP[8];
    float4 rbV[2];

    // Prologue prefetch (kt = 0)
#pragma unroll
    for (int p = 0; p < 8; p++) {
        int v = tid + NTHREADS * p, row = v >> 4, kk = v & 15;
        int m = tm0 + row;
        raP[p] = (m < S_ && kk < S_) ? P[(size_t)m * S_ + kk] : 0.f;
    }
#pragma unroll
    for (int p = 0; p < 2; p++) {
        int v = tid + NTHREADS * p, kk = v >> 5, n4 = (v & 31) * 4;
        rbV[p] = (kk < S_) ? *(const float4*)&Vp[(size_t)kk * (B_ * D_) + tn0 + n4]
                           : make_float4(0.f, 0.f, 0.f, 0.f);
    }

    const int NKT = (S_ + BK - 1) / BK;  // 37
    for (int kt = 0; kt < NKT; kt++) {
#pragma unroll
        for (int p = 0; p < 8; p++) {
            int v = tid + NTHREADS * p;
            As[v & 15][v >> 4] = raP[p];
        }
#pragma unroll
        for (int p = 0; p < 2; p++) {
            int v = tid + NTHREADS * p;
            *(float4*)&Bs[v >> 5][(v & 31) * 4] = rbV[p];
        }
        __syncthreads();

        if (kt + 1 < NKT) {
            const int k0 = (kt + 1) * BK;
#pragma unroll
            for (int p = 0; p < 8; p++) {
                int v = tid + NTHREADS * p, row = v >> 4, kk = v & 15;
                int m = tm0 + row, k = k0 + kk;
                raP[p] = (m < S_ && k < S_) ? P[(size_t)m * S_ + k] : 0.f;
            }
#pragma unroll
            for (int p = 0; p < 2; p++) {
                int v = tid + NTHREADS * p, kk = v >> 5, n4 = (v & 31) * 4;
                int k = k0 + kk;
                rbV[p] = (k < S_) ? *(const float4*)&Vp[(size_t)k * (B_ * D_) + tn0 + n4]
                                  : make_float4(0.f, 0.f, 0.f, 0.f);
            }
        }

#pragma unroll
        for (int k = 0; k < BK; k++) {
            float a[TM];
            *(float4*)&a[0] = *(const float4*)&As[k][ty * TM];
            *(float4*)&a[4] = *(const float4*)&As[k][ty * TM + 4];
            float4 t0 = *(const float4*)&Bs[k][tx * TN];
            float4 t1 = *(const float4*)&Bs[k][tx * TN + 4];
            float2 bb[4] = { make_float2(t0.x, t0.y), make_float2(t0.z, t0.w),
                             make_float2(t1.x, t1.y), make_float2(t1.z, t1.w) };
#pragma unroll
            for (int i = 0; i < TM; i++) {
                float2 a2 = make_float2(a[i], a[i]);
#pragma unroll
                for (int j = 0; j < TN / 2; j++)
                    acc2[i][j] = ffma2(a2, bb[j], acc2[i][j]);
            }
        }
        __syncthreads();
    }

    const int n0 = tn0 + tx * TN;
    const int bb_ = n0 / D_;
    const int d0  = n0 % D_;
#pragma unroll
    for (int i = 0; i < TM; i++) {
        int m = tm0 + ty * TM + i;
        if (m < S_) {
            float* dst = &g_O[((size_t)bb_ * S_ + m) * E_ + h * D_ + d0];
            *(float4*)&dst[0] = make_float4(acc2[i][0].x, acc2[i][0].y,
                                            acc2[i][1].x, acc2[i][1].y);
            *(float4*)&dst[4] = make_float4(acc2[i][2].x, acc2[i][2].y,
                                            acc2[i][3].x, acc2[i][3].y);
        }
    }
}

// ---------------------------------------------------------------------------
extern "C" void kernel_launch(void* const* d_in, const int* in_sizes, int n_in,
                              void* d_out, int out_size)
{
    const float* hidden = (const float*)d_in[0];
    const float* v_w    = (const float*)d_in[3];
    const float* v_b    = (const float*)d_in[4];
    const float* out_w  = (const float*)d_in[5];
    const float* out_b  = (const float*)d_in[6];
    const float* s_bias = (const float*)d_in[8];
    float* out = (float*)d_out;

    dim3 g_big(E_ / BN, (M_ + BM - 1) / BM);            // 8 x 73
    dim3 g_pv(E_ / BN, (S_ + BM - 1) / BM, H_);         // 8 x 5 x 16

    gemm_nt_kernel<0><<<g_big, NTHREADS>>>(hidden, v_w, v_b, nullptr);
    softmax_kernel<<<H_ * S_, 256>>>(s_bias);
    gemm_pv_kernel<<<g_pv, NTHREADS>>>();
    gemm_nt_kernel<1><<<g_big, NTHREADS>>>(nullptr, out_w, out_b, out);
}

// round 4
// speedup vs baseline: 4.0644x; 2.5655x over previous
#include <cuda_runtime.h>
#include <cuda_bf16.h>
#include <cstdint>

#define B_ 16
#define S_ 577
#define SP 640               // padded seq (K padding for GEMM2)
#define E_ 1024
#define H_ 16
#define D_ 64
#define M_ (B_ * S_)         // 9232

typedef __nv_bfloat16 bf16;

// ---------------- scratch (static device globals, zero-init at load) -------
__device__ bf16 g_Ah[(size_t)M_ * E_],  g_Al[(size_t)M_ * E_];   // split hidden
__device__ bf16 g_Wvh[(size_t)E_ * E_], g_Wvl[(size_t)E_ * E_];  // split v_w
__device__ bf16 g_Woh[(size_t)E_ * E_], g_Wol[(size_t)E_ * E_];  // split out_w
__device__ bf16 g_Vh[(size_t)H_ * E_ * SP], g_Vl[(size_t)H_ * E_ * SP]; // V^T [h][(b,d)][s]
__device__ bf16 g_Ph[(size_t)H_ * S_ * SP], g_Pl[(size_t)H_ * S_ * SP]; // softmax(P)
__device__ bf16 g_Oh[(size_t)M_ * E_],  g_Ol[(size_t)M_ * E_];   // attn out split

// ---------------- PTX helpers (all portable: sm_80-level) -------------------
__device__ __forceinline__ uint32_t smem_u32(const void* p) {
    uint32_t a;
    asm("{ .reg .u64 t; cvta.to.shared.u64 t, %1; cvt.u32.u64 %0, t; }" : "=r"(a) : "l"(p));
    return a;
}
__device__ __forceinline__ void cp16(uint32_t dst, const void* src) {
    asm volatile("cp.async.cg.shared.global [%0], [%1], 16;" :: "r"(dst), "l"(src));
}
#define CP_COMMIT() asm volatile("cp.async.commit_group;" ::: "memory")
#define CP_WAIT2()  asm volatile("cp.async.wait_group 2;" ::: "memory")

__device__ __forceinline__ void ldsm4(uint32_t* r, uint32_t addr) {
    asm volatile("ldmatrix.sync.aligned.m8n8.x4.shared.b16 {%0,%1,%2,%3}, [%4];"
                 : "=r"(r[0]), "=r"(r[1]), "=r"(r[2]), "=r"(r[3]) : "r"(addr));
}
__device__ __forceinline__ void ldsm2(uint32_t* r, uint32_t addr) {
    asm volatile("ldmatrix.sync.aligned.m8n8.x2.shared.b16 {%0,%1}, [%2];"
                 : "=r"(r[0]), "=r"(r[1]) : "r"(addr));
}
__device__ __forceinline__ void mma_bf16(float* c, const uint32_t* a, const uint32_t* b) {
    asm volatile("mma.sync.aligned.m16n8k16.row.col.f32.bf16.bf16.f32 "
                 "{%0,%1,%2,%3}, {%4,%5,%6,%7}, {%8,%9}, {%0,%1,%2,%3};"
                 : "+f"(c[0]), "+f"(c[1]), "+f"(c[2]), "+f"(c[3])
                 : "r"(a[0]), "r"(a[1]), "r"(a[2]), "r"(a[3]), "r"(b[0]), "r"(b[1]));
}

// ---------------- tiling ----------------------------------------------------
// CTA tile 128x128, KBLK=32. SMEM row = 128B = 8 x 16B chunks:
// chunk c = split*4 + kc (kc = 16B k-chunk 0..3). Physical chunk = c ^ (row&7)
// -> ldmatrix's 8 row-addresses land in 8 distinct 16B columns (conflict-free).
#define KBLK 32
#define NSTAGE 3
#define TILE_BYTES 16384                     // 128 rows x 128B (hi|lo interleaved)
#define STAGE_BYTES (2 * TILE_BYTES)         // A tile + B tile
#define SMEM_SZ (NSTAGE * STAGE_BYTES)       // 98304

__device__ __forceinline__ uint32_t swz(int row, int c) {
    return (uint32_t)(row * 128 + ((c ^ (row & 7)) << 4));
}

// ---------------------------------------------------------------------------
// bf16x3 HMMA GEMM (mma.sync m16n8k16), NT: C[m,n] = sum_k A[m,k]*B[n,k]
// MODE 0: V-proj   A=hidden split,B=v_w split,  K=1024 -> g_Vh/g_Vl (V^T, +v_b)
// MODE 1: P@V      A=P split,     B=V^T split,  K=640  -> g_Oh/g_Ol
// MODE 2: out-proj A=O split,     B=out_w split,K=1024 -> d_out fp32 (+out_b)
// ---------------------------------------------------------------------------
template <int MODE>
__global__ __launch_bounds__(256, 2)
void gemm_hmma(const float* __restrict__ bias, float* __restrict__ outp)
{
    extern __shared__ __align__(1024) char smem[];
    const uint32_t sb = smem_u32(smem);
    const int tid  = threadIdx.x;
    const int wid  = tid >> 5, lane = tid & 31;
    const int wm   = wid & 1, wn = wid >> 1;      // warp grid 2m x 4n
    const int gid  = lane >> 2, tig = lane & 3;

    const bf16 *Ah, *Al, *Bh, *Bl;
    int Mrows, pitch, kiter;
    if (MODE == 0) {
        Ah = g_Ah; Al = g_Al; Bh = g_Wvh; Bl = g_Wvl;
        Mrows = M_; pitch = E_; kiter = E_ / KBLK;
    } else if (MODE == 1) {
        const size_t ho = (size_t)blockIdx.z;
        Ah = g_Ph + ho * S_ * SP; Al = g_Pl + ho * S_ * SP;
        Bh = g_Vh + ho * E_ * SP; Bl = g_Vl + ho * E_ * SP;
        Mrows = S_; pitch = SP; kiter = SP / KBLK;
    } else {
        Ah = g_Oh; Al = g_Ol; Bh = g_Woh; Bl = g_Wol;
        Mrows = M_; pitch = E_; kiter = E_ / KBLK;
    }
    const int tm0 = blockIdx.y * 128, tn0 = blockIdx.x * 128;

    // per-thread cp.async lanes: 8 x 16B chunks/stage
    const bf16* srcp[8];
    uint32_t dstoff[8];
#pragma unroll
    for (int p = 0; p < 8; p++) {
        const int id   = p * 256 + tid;       // 0..2047
        const int tile = id >> 10;            // 0 = A, 1 = B
        const int rem  = id & 1023;
        const int row  = rem >> 3;
        const int c    = rem & 7;
        const int sp   = c >> 2, kc = c & 3;
        int grow;
        const bf16* base;
        if (tile == 0) {
            grow = tm0 + row;
            if (grow >= Mrows) grow = 0;      // clamp: garbage rows never stored
            base = sp ? Al : Ah;
        } else {
            grow = tn0 + row;                 // N = 1024 always exact
            base = sp ? Bl : Bh;
        }
        srcp[p]   = base + (size_t)grow * pitch + kc * 8;
        dstoff[p] = (uint32_t)tile * TILE_BYTES + swz(row, c);
    }

    auto do_load = [&](int kt) {
        if (kt < kiter) {
            const uint32_t sbase = sb + (uint32_t)(kt % NSTAGE) * STAGE_BYTES;
            const int koff = kt * KBLK;
#pragma unroll
            for (int p = 0; p < 8; p++)
                cp16(sbase + dstoff[p], srcp[p] + koff);
        }
        CP_COMMIT();
    };

    float acc[4][4][4];
#pragma unroll
    for (int i = 0; i < 4; i++)
#pragma unroll
        for (int j = 0; j < 4; j++)
#pragma unroll
            for (int q = 0; q < 4; q++) acc[i][j][q] = 0.f;

    do_load(0); do_load(1); do_load(2);

    for (int kt = 0; kt < kiter; kt++) {
        CP_WAIT2();
        __syncthreads();
        const uint32_t Ab = sb + (uint32_t)(kt % NSTAGE) * STAGE_BYTES;
        const uint32_t Bb = Ab + TILE_BYTES;

#pragma unroll
        for (int ks = 0; ks < 2; ks++) {
            // B fragments: [split][nt][2]
            uint32_t bf[2][4][2];
#pragma unroll
            for (int sp = 0; sp < 2; sp++)
#pragma unroll
                for (int nt = 0; nt < 4; nt++) {
                    const int nr = wn * 32 + nt * 8 + (lane & 7);
                    const int c  = sp * 4 + ks * 2 + ((lane >> 3) & 1);
                    ldsm2(bf[sp][nt], Bb + swz(nr, c));
                }
#pragma unroll
            for (int mt = 0; mt < 4; mt++) {
                uint32_t ah[4], al[4];
                {
                    const int mr = wm * 64 + mt * 16 + (lane & 15);
                    const int kh = lane >> 4;
                    ldsm4(ah, Ab + swz(mr, 0 * 4 + ks * 2 + kh));
                    ldsm4(al, Ab + swz(mr, 1 * 4 + ks * 2 + kh));
                }
#pragma unroll
                for (int nt = 0; nt < 4; nt++) {
                    mma_bf16(acc[mt][nt], ah, bf[0][nt]);   // hi*hi
                    mma_bf16(acc[mt][nt], ah, bf[1][nt]);   // hi*lo
                    mma_bf16(acc[mt][nt], al, bf[0][nt]);   // lo*hi
                }
            }
        }
        __syncthreads();
        do_load(kt + 3);
    }

    // ---------------- epilogue (register accumulators) ----------------------
#pragma unroll
    for (int mt = 0; mt < 4; mt++) {
#pragma unroll
        for (int half = 0; half < 2; half++) {
            const int m = tm0 + wm * 64 + mt * 16 + gid + half * 8;
            if (m >= Mrows) continue;
            int bb = 0, s = 0;
            if (MODE == 0) { bb = m / S_; s = m - bb * S_; }
#pragma unroll
            for (int nt = 0; nt < 4; nt++) {
                const int n0 = tn0 + wn * 32 + nt * 8 + tig * 2;
#pragma unroll
                for (int j = 0; j < 2; j++) {
                    const int n = n0 + j;
                    float v = acc[mt][nt][half * 2 + j];
                    if (MODE == 0) {
                        v += bias[n];
                        const size_t a = ((size_t)(n >> 6) * (B_ * D_)
                                          + (size_t)bb * D_ + (n & 63)) * SP + s;
                        const bf16 h = __float2bfloat16(v);
                        g_Vh[a] = h;
                        g_Vl[a] = __float2bfloat16(v - __bfloat162float(h));
                    } else if (MODE == 1) {
                        const size_t a = ((size_t)(n >> 6) * S_ + m) * E_
                                         + (size_t)blockIdx.z * D_ + (n & 63);
                        const bf16 h = __float2bfloat16(v);
                        g_Oh[a] = h;
                        g_Ol[a] = __float2bfloat16(v - __bfloat162float(h));
                    } else {
                        outp[(size_t)m * E_ + n] = v + bias[n];
                    }
                }
            }
        }
    }
}

// ---------------------------------------------------------------------------
// input splits
// ---------------------------------------------------------------------------
template <int W>
__global__ void split_fixed(const float* __restrict__ src, size_t n)
{
    bf16* dh = (W == 0) ? g_Ah : (W == 1) ? g_Wvh : g_Woh;
    bf16* dl = (W == 0) ? g_Al : (W == 1) ? g_Wvl : g_Wol;
    const size_t stride = (size_t)gridDim.x * blockDim.x;
    for (size_t i = (size_t)blockIdx.x * blockDim.x + threadIdx.x; i < n; i += stride) {
        const float v = src[i];
        const bf16 h = __float2bfloat16(v);
        dh[i] = h;
        dl[i] = __float2bfloat16(v - __bfloat162float(h));
    }
}

// ---------------------------------------------------------------------------
// softmax(share_bias) -> split bf16 P, K padded to SP with zeros.
// Q path cancels: softmax is shift-invariant along the last axis.
// ---------------------------------------------------------------------------
__global__ __launch_bounds__(256)
void softmax_kernel(const float* __restrict__ bias)
{
    const int row = blockIdx.x;                     // h*S_ + i
    const float* __restrict__ src = bias + (size_t)row * S_;
    bf16* __restrict__ dh = g_Ph + (size_t)row * SP;
    bf16* __restrict__ dl = g_Pl + (size_t)row * SP;
    const int tid = threadIdx.x;

    __shared__ float shm[8], shs[8];

    float v0 = (tid       < S_) ? src[tid]       : -3.0e38f;
    float v1 = (tid + 256 < S_) ? src[tid + 256] : -3.0e38f;
    float v2 = (tid + 512 < S_) ? src[tid + 512] : -3.0e38f;

    float mx = fmaxf(v0, fmaxf(v1, v2));
#pragma unroll
    for (int o = 16; o > 0; o >>= 1) mx = fmaxf(mx, __shfl_xor_sync(0xffffffffu, mx, o));
    if ((tid & 31) == 0) shm[tid >> 5] = mx;
    __syncthreads();
    mx = shm[0];
#pragma unroll
    for (int w = 1; w < 8; w++) mx = fmaxf(mx, shm[w]);

    float e0 = __expf(v0 - mx), e1 = __expf(v1 - mx), e2 = __expf(v2 - mx);
    float s = e0 + e1 + e2;
#pragma unroll
    for (int o = 16; o > 0; o >>= 1) s += __shfl_xor_sync(0xffffffffu, s, o);
    if ((tid & 31) == 0) shs[tid >> 5] = s;
    __syncthreads();
    s = shs[0];
#pragma unroll
    for (int w = 1; w < 8; w++) s += shs[w];
    const float inv = 1.0f / s;

#pragma unroll
    for (int q = 0; q < 3; q++) {
        const int c = tid + q * 256;
        if (c < SP) {
            const float pv = (c < S_) ? (q == 0 ? e0 : q == 1 ? e1 : e2) * inv : 0.f;
            const bf16 h = __float2bfloat16(pv);
            dh[c] = h;
            dl[c] = __float2bfloat16(pv - __bfloat162float(h));
        }
    }
}

// ---------------------------------------------------------------------------
extern "C" void kernel_launch(void* const* d_in, const int* in_sizes, int n_in,
                              void* d_out, int out_size)
{
    const float* hidden = (const float*)d_in[0];
    const float* v_w    = (const float*)d_in[3];
    const float* v_b    = (const float*)d_in[4];
    const float* out_w  = (const float*)d_in[5];
    const float* out_b  = (const float*)d_in[6];
    const float* s_bias = (const float*)d_in[8];
    float* out = (float*)d_out;

    cudaFuncSetAttribute(gemm_hmma<0>, cudaFuncAttributeMaxDynamicSharedMemorySize, SMEM_SZ);
    cudaFuncSetAttribute(gemm_hmma<1>, cudaFuncAttributeMaxDynamicSharedMemorySize, SMEM_SZ);
    cudaFuncSetAttribute(gemm_hmma<2>, cudaFuncAttributeMaxDynamicSharedMemorySize, SMEM_SZ);

    split_fixed<0><<<2048, 256>>>(hidden, (size_t)M_ * E_);
    split_fixed<1><<<512, 256>>>(v_w, (size_t)E_ * E_);
    split_fixed<2><<<512, 256>>>(out_w, (size_t)E_ * E_);
    softmax_kernel<<<H_ * S_, 256>>>(s_bias);

    gemm_hmma<0><<<dim3(8, 73),    256, SMEM_SZ>>>(v_b, nullptr);   // V projection
    gemm_hmma<1><<<dim3(8, 5, 16), 256, SMEM_SZ>>>(nullptr, nullptr); // P @ V
    gemm_hmma<2><<<dim3(8, 73),    256, SMEM_SZ>>>(out_b, out);     // out projection
}

// round 5
// speedup vs baseline: 5.6243x; 1.3838x over previous
#include <cuda_runtime.h>
#include <cuda_fp16.h>
#include <cstdint>

#define B_ 16
#define S_ 577
#define SP 640               // padded seq (K padding for GEMM2)
#define E_ 1024
#define H_ 16
#define D_ 64
#define M_ (B_ * S_)         // 9232

// ---------------- scratch (static device globals, zero-init at load) -------
__device__ half g_Ah[(size_t)M_ * E_];                            // hidden hi
__device__ half g_Wvh[(size_t)E_ * E_], g_Wvl[(size_t)E_ * E_];   // v_w hi/lo
__device__ half g_Woh[(size_t)E_ * E_], g_Wol[(size_t)E_ * E_];   // out_w hi/lo
__device__ half g_Vh[(size_t)H_ * E_ * SP], g_Vl[(size_t)H_ * E_ * SP]; // V^T [h][(b,d)][s]
__device__ half g_Ph[(size_t)H_ * S_ * SP];                       // softmax(P) hi
__device__ half g_Oh[(size_t)M_ * E_];                            // attn out hi

// ---------------- PTX helpers (portable sm_80-level) ------------------------
__device__ __forceinline__ uint32_t smem_u32(const void* p) {
    uint32_t a;
    asm("{ .reg .u64 t; cvta.to.shared.u64 t, %1; cvt.u32.u64 %0, t; }" : "=r"(a) : "l"(p));
    return a;
}
__device__ __forceinline__ void cp16(uint32_t dst, const void* src) {
    asm volatile("cp.async.cg.shared.global [%0], [%1], 16;" :: "r"(dst), "l"(src));
}
#define CP_COMMIT() asm volatile("cp.async.commit_group;" ::: "memory")
#define CP_WAIT2()  asm volatile("cp.async.wait_group 2;" ::: "memory")

__device__ __forceinline__ void ldsm4(uint32_t* r, uint32_t addr) {
    asm volatile("ldmatrix.sync.aligned.m8n8.x4.shared.b16 {%0,%1,%2,%3}, [%4];"
                 : "=r"(r[0]), "=r"(r[1]), "=r"(r[2]), "=r"(r[3]) : "r"(addr));
}
__device__ __forceinline__ void ldsm2(uint32_t* r, uint32_t addr) {
    asm volatile("ldmatrix.sync.aligned.m8n8.x2.shared.b16 {%0,%1}, [%2];"
                 : "=r"(r[0]), "=r"(r[1]) : "r"(addr));
}
__device__ __forceinline__ void mma_f16(float* c, const uint32_t* a, const uint32_t* b) {
    asm volatile("mma.sync.aligned.m16n8k16.row.col.f32.f16.f16.f32 "
                 "{%0,%1,%2,%3}, {%4,%5,%6,%7}, {%8,%9}, {%0,%1,%2,%3};"
                 : "+f"(c[0]), "+f"(c[1]), "+f"(c[2]), "+f"(c[3])
                 : "r"(a[0]), "r"(a[1]), "r"(a[2]), "r"(a[3]), "r"(b[0]), "r"(b[1]));
}

// ---------------- tiling ----------------------------------------------------
// CTA tile 128x128, KBLK=32. SMEM row = 128B = 8 x 16B chunks, physical chunk
// = c ^ (row&7). A tile uses chunks c in [0,4) (k 0..31); B uses all 8
// (split*4 + kc). 8 ldmatrix row-addresses -> 8 distinct chunks: conflict-free.
#define KBLK 32
#define NSTAGE 3
#define TILE_BYTES 16384
#define STAGE_BYTES (2 * TILE_BYTES)
#define SMEM_SZ (NSTAGE * STAGE_BYTES)       // 98304

__device__ __forceinline__ uint32_t swz(int row, int c) {
    return (uint32_t)(row * 128 + ((c ^ (row & 7)) << 4));
}

// ---------------------------------------------------------------------------
// fp16x2 HMMA GEMM, NT: C[m,n] = sum_k A[m,k]*B[n,k];  C = Ah*(Bh + Bl)
// MODE 0: V-proj   A=g_Ah, B=v_w split,  K=1024 -> g_Vh/g_Vl (V^T, +v_b)
// MODE 1: P@V      A=g_Ph, B=V^T split,  K=640  -> g_Oh
// MODE 2: out-proj A=g_Oh, B=out_w split,K=1024 -> d_out fp32 (+out_b)
// ---------------------------------------------------------------------------
template <int MODE>
__global__ __launch_bounds__(256, 2)
void gemm_hmma(const float* __restrict__ bias, float* __restrict__ outp)
{
    extern __shared__ __align__(1024) char smem[];
    const uint32_t sb = smem_u32(smem);
    const int tid  = threadIdx.x;
    const int wid  = tid >> 5, lane = tid & 31;
    const int wm   = wid & 1, wn = wid >> 1;      // warp grid 2m x 4n
    const int gid  = lane >> 2, tig = lane & 3;

    const half *Ah, *Bh, *Bl;
    int Mrows, pitch, kiter;
    if (MODE == 0) {
        Ah = g_Ah; Bh = g_Wvh; Bl = g_Wvl;
        Mrows = M_; pitch = E_; kiter = E_ / KBLK;
    } else if (MODE == 1) {
        const size_t ho = (size_t)blockIdx.z;
        Ah = g_Ph + ho * S_ * SP;
        Bh = g_Vh + ho * E_ * SP; Bl = g_Vl + ho * E_ * SP;
        Mrows = S_; pitch = SP; kiter = SP / KBLK;
    } else {
        Ah = g_Oh; Bh = g_Woh; Bl = g_Wol;
        Mrows = M_; pitch = E_; kiter = E_ / KBLK;
    }
    const int tm0 = blockIdx.y * 128, tn0 = blockIdx.x * 128;

    // 6 x 16B cp.async chunks per thread per stage (A:512 chunks, B:1024)
    auto do_load = [&](int kt) {
        if (kt < kiter) {
            const uint32_t sbase = sb + (uint32_t)(kt % NSTAGE) * STAGE_BYTES;
            const int koff = kt * KBLK;
#pragma unroll
            for (int p = 0; p < 6; p++) {
                const int id = p * 256 + tid;
                if (id < 512) {                       // A (hi only)
                    const int row = id >> 2, c = id & 3;
                    int grow = tm0 + row;
                    if (grow >= Mrows) grow = 0;      // clamp: never stored
                    cp16(sbase + swz(row, c),
                         Ah + (size_t)grow * pitch + koff + c * 8);
                } else {                              // B (hi|lo interleaved)
                    const int idb = id - 512;
                    const int row = idb >> 3, c = idb & 7;
                    const half* base = (c >> 2) ? Bl : Bh;
                    cp16(sbase + TILE_BYTES + swz(row, c),
                         base + (size_t)(tn0 + row) * pitch + koff + (c & 3) * 8);
                }
            }
        }
        CP_COMMIT();
    };

    float acc[4][4][4];
#pragma unroll
    for (int i = 0; i < 4; i++)
#pragma unroll
        for (int j = 0; j < 4; j++)
#pragma unroll
            for (int q = 0; q < 4; q++) acc[i][j][q] = 0.f;

    do_load(0); do_load(1); do_load(2);

    for (int kt = 0; kt < kiter; kt++) {
        CP_WAIT2();
        __syncthreads();
        const uint32_t Ab = sb + (uint32_t)(kt % NSTAGE) * STAGE_BYTES;
        const uint32_t Bb = Ab + TILE_BYTES;

#pragma unroll
        for (int ks = 0; ks < 2; ks++) {
            uint32_t bf[2][4][2];
#pragma unroll
            for (int sp = 0; sp < 2; sp++)
#pragma unroll
                for (int nt = 0; nt < 4; nt++) {
                    const int nr = wn * 32 + nt * 8 + (lane & 7);
                    const int c  = sp * 4 + ks * 2 + ((lane >> 3) & 1);
                    ldsm2(bf[sp][nt], Bb + swz(nr, c));
                }
#pragma unroll
            for (int mt = 0; mt < 4; mt++) {
                uint32_t ah[4];
                {
                    const int mr = wm * 64 + mt * 16 + (lane & 15);
                    const int kh = lane >> 4;
                    ldsm4(ah, Ab + swz(mr, ks * 2 + kh));
                }
#pragma unroll
                for (int nt = 0; nt < 4; nt++) {
                    mma_f16(acc[mt][nt], ah, bf[0][nt]);   // Ah*Bh
                    mma_f16(acc[mt][nt], ah, bf[1][nt]);   // Ah*Bl
                }
            }
        }
        __syncthreads();
        do_load(kt + 3);
    }

    // ---------------- epilogue ----------------------------------------------
#pragma unroll
    for (int mt = 0; mt < 4; mt++) {
#pragma unroll
        for (int half_ = 0; half_ < 2; half_++) {
            const int m = tm0 + wm * 64 + mt * 16 + gid + half_ * 8;
            if (m >= Mrows) continue;
            int bb = 0, s = 0;
            if (MODE == 0) { bb = m / S_; s = m - bb * S_; }
#pragma unroll
            for (int nt = 0; nt < 4; nt++) {
                const int n0 = tn0 + wn * 32 + nt * 8 + tig * 2;
#pragma unroll
                for (int j = 0; j < 2; j++) {
                    const int n = n0 + j;
                    float v = acc[mt][nt][half_ * 2 + j];
                    if (MODE == 0) {
                        v += bias[n];
                        const size_t a = ((size_t)(n >> 6) * (B_ * D_)
                                          + (size_t)bb * D_ + (n & 63)) * SP + s;
                        const half h = __float2half_rn(v);
                        g_Vh[a] = h;
                        g_Vl[a] = __float2half_rn(v - __half2float(h));
                    } else if (MODE == 1) {
                        const size_t a = ((size_t)(n >> 6) * S_ + m) * E_
                                         + (size_t)blockIdx.z * D_ + (n & 63);
                        g_Oh[a] = __float2half_rn(v);
                    } else {
                        outp[(size_t)m * E_ + n] = v + bias[n];
                    }
                }
            }
        }
    }
}

// ---------------------------------------------------------------------------
// input conversions
// ---------------------------------------------------------------------------
__global__ void split_hidden(const float* __restrict__ src, size_t n)
{
    const size_t stride = (size_t)gridDim.x * blockDim.x;
    for (size_t i = (size_t)blockIdx.x * blockDim.x + threadIdx.x; i < n; i += stride)
        g_Ah[i] = __float2half_rn(src[i]);
}

template <int W>
__global__ void split_weight(const float* __restrict__ src, size_t n)
{
    half* dh = (W == 0) ? g_Wvh : g_Woh;
    half* dl = (W == 0) ? g_Wvl : g_Wol;
    const size_t stride = (size_t)gridDim.x * blockDim.x;
    for (size_t i = (size_t)blockIdx.x * blockDim.x + threadIdx.x; i < n; i += stride) {
        const float v = src[i];
        const half h = __float2half_rn(v);
        dh[i] = h;
        dl[i] = __float2half_rn(v - __half2float(h));
    }
}

// ---------------------------------------------------------------------------
// softmax(share_bias) -> g_Ph (fp16), K padded to SP with zeros.
// Q path cancels: softmax is shift-invariant along the last axis.
// ---------------------------------------------------------------------------
__global__ __launch_bounds__(256)
void softmax_kernel(const float* __restrict__ bias)
{
    const int row = blockIdx.x;                     // h*S_ + i
    const float* __restrict__ src = bias + (size_t)row * S_;
    half* __restrict__ dh = g_Ph + (size_t)row * SP;
    const int tid = threadIdx.x;

    __shared__ float shm[8], shs[8];

    float v0 = (tid       < S_) ? src[tid]       : -3.0e38f;
    float v1 = (tid + 256 < S_) ? src[tid + 256] : -3.0e38f;
    float v2 = (tid + 512 < S_) ? src[tid + 512] : -3.0e38f;

    float mx = fmaxf(v0, fmaxf(v1, v2));
#pragma unroll
    for (int o = 16; o > 0; o >>= 1) mx = fmaxf(mx, __shfl_xor_sync(0xffffffffu, mx, o));
    if ((tid & 31) == 0) shm[tid >> 5] = mx;
    __syncthreads();
    mx = shm[0];
#pragma unroll
    for (int w = 1; w < 8; w++) mx = fmaxf(mx, shm[w]);

    float e0 = __expf(v0 - mx), e1 = __expf(v1 - mx), e2 = __expf(v2 - mx);
    float s = e0 + e1 + e2;
#pragma unroll
    for (int o = 16; o > 0; o >>= 1) s += __shfl_xor_sync(0xffffffffu, s, o);
    if ((tid & 31) == 0) shs[tid >> 5] = s;
    __syncthreads();
    s = shs[0];
#pragma unroll
    for (int w = 1; w < 8; w++) s += shs[w];
    const float inv = 1.0f / s;

#pragma unroll
    for (int q = 0; q < 3; q++) {
        const int c = tid + q * 256;
        if (c < SP) {
            const float pv = (c < S_) ? (q == 0 ? e0 : q == 1 ? e1 : e2) * inv : 0.f;
            dh[c] = __float2half_rn(pv);
        }
    }
}

// ---------------------------------------------------------------------------
extern "C" void kernel_launch(void* const* d_in, const int* in_sizes, int n_in,
                              void* d_out, int out_size)
{
    const float* hidden = (const float*)d_in[0];
    const float* v_w    = (const float*)d_in[3];
    const float* v_b    = (const float*)d_in[4];
    const float* out_w  = (const float*)d_in[5];
    const float* out_b  = (const float*)d_in[6];
    const float* s_bias = (const float*)d_in[8];
    float* out = (float*)d_out;

    cudaFuncSetAttribute(gemm_hmma<0>, cudaFuncAttributeMaxDynamicSharedMemorySize, SMEM_SZ);
    cudaFuncSetAttribute(gemm_hmma<1>, cudaFuncAttributeMaxDynamicSharedMemorySize, SMEM_SZ);
    cudaFuncSetAttribute(gemm_hmma<2>, cudaFuncAttributeMaxDynamicSharedMemorySize, SMEM_SZ);

    split_hidden<<<2048, 256>>>(hidden, (size_t)M_ * E_);
    split_weight<0><<<512, 256>>>(v_w, (size_t)E_ * E_);
    split_weight<1><<<512, 256>>>(out_w, (size_t)E_ * E_);
    softmax_kernel<<<H_ * S_, 256>>>(s_bias);

    gemm_hmma<0><<<dim3(8, 73),    256, SMEM_SZ>>>(v_b, nullptr);     // V projection
    gemm_hmma<1><<<dim3(8, 5, 16), 256, SMEM_SZ>>>(nullptr, nullptr); // P @ V
    gemm_hmma<2><<<dim3(8, 73),    256, SMEM_SZ>>>(out_b, out);       // out projection
}

// round 6
// speedup vs baseline: 8.5414x; 1.5187x over previous
#include <cuda_runtime.h>
#include <cuda_fp16.h>
#include <cstdint>

#define B_ 16
#define S_ 577
#define SP 640               // padded seq (K padding for GEMM2)
#define E_ 1024
#define H_ 16
#define D_ 64
#define M_ (B_ * S_)         // 9232

// ---------------- scratch (static device globals, zero-init at load) -------
__device__ half g_Ah[(size_t)M_ * E_];                   // hidden fp16
__device__ half g_Wv[(size_t)E_ * E_];                   // v_w fp16
__device__ half g_Wo[(size_t)E_ * E_];                   // out_w fp16
__device__ half g_Vh[(size_t)H_ * E_ * SP];              // V^T [h][(b,d)][s] (pad=0)
__device__ half g_Ph[(size_t)H_ * S_ * SP];              // softmax(P) (pad=0)
__device__ half g_Oh[(size_t)M_ * E_];                   // attn out fp16

// ---------------- PTX helpers (portable sm_80-level) ------------------------
__device__ __forceinline__ uint32_t smem_u32(const void* p) {
    uint32_t a;
    asm("{ .reg .u64 t; cvta.to.shared.u64 t, %1; cvt.u32.u64 %0, t; }" : "=r"(a) : "l"(p));
    return a;
}
__device__ __forceinline__ void cp16(uint32_t dst, const void* src) {
    asm volatile("cp.async.cg.shared.global [%0], [%1], 16;" :: "r"(dst), "l"(src));
}
#define CP_COMMIT() asm volatile("cp.async.commit_group;" ::: "memory")
#define CP_WAIT2()  asm volatile("cp.async.wait_group 2;" ::: "memory")

__device__ __forceinline__ void ldsm4(uint32_t* r, uint32_t addr) {
    asm volatile("ldmatrix.sync.aligned.m8n8.x4.shared.b16 {%0,%1,%2,%3}, [%4];"
                 : "=r"(r[0]), "=r"(r[1]), "=r"(r[2]), "=r"(r[3]) : "r"(addr));
}
__device__ __forceinline__ void ldsm2(uint32_t* r, uint32_t addr) {
    asm volatile("ldmatrix.sync.aligned.m8n8.x2.shared.b16 {%0,%1}, [%2];"
                 : "=r"(r[0]), "=r"(r[1]) : "r"(addr));
}
__device__ __forceinline__ void mma_f16(float* c, const uint32_t* a, const uint32_t* b) {
    asm volatile("mma.sync.aligned.m16n8k16.row.col.f32.f16.f16.f32 "
                 "{%0,%1,%2,%3}, {%4,%5,%6,%7}, {%8,%9}, {%0,%1,%2,%3};"
                 : "+f"(c[0]), "+f"(c[1]), "+f"(c[2]), "+f"(c[3])
                 : "r"(a[0]), "r"(a[1]), "r"(a[2]), "r"(a[3]), "r"(b[0]), "r"(b[1]));
}

// ---------------- tiling ----------------------------------------------------
// CTA tile 128x128, KBLK=32. ONE combined SMEM row per r (128B = 8 x 16B
// chunks): chunks 0-3 = A row r (k 0..31), chunks 4-7 = B row r (k 0..31).
// Physical chunk = c ^ (row&7): ldmatrix's 8 row-addresses -> 8 distinct
// chunks (conflict-free, same verified swizzle as before).
#define KBLK 32
#define NSTAGE 3
#define STAGE_BYTES 16384                    // 128 rows x 128B
#define SMEM_SZ (NSTAGE * STAGE_BYTES)       // 49152

__device__ __forceinline__ uint32_t swz(int row, int c) {
    return (uint32_t)(row * 128 + ((c ^ (row & 7)) << 4));
}

// ---------------------------------------------------------------------------
// fp16 HMMA GEMM (single term), NT: C[m,n] = sum_k A[m,k]*B[n,k]
// MODE 0: V-proj   A=g_Ah, B=g_Wv, K=1024 -> g_Vh (V^T scatter, +v_b)
// MODE 1: P@V      A=g_Ph, B=g_Vh, K=640  -> g_Oh
// MODE 2: out-proj A=g_Oh, B=g_Wo, K=1024 -> d_out fp32 (+out_b)
// ---------------------------------------------------------------------------
template <int MODE>
__global__ __launch_bounds__(256, 2)
void gemm_hmma(const float* __restrict__ bias, float* __restrict__ outp)
{
    extern __shared__ __align__(1024) char smem[];
    const uint32_t sb = smem_u32(smem);
    const int tid  = threadIdx.x;
    const int wid  = tid >> 5, lane = tid & 31;
    const int wm   = wid & 1, wn = wid >> 1;      // warp grid 2m x 4n
    const int gid  = lane >> 2, tig = lane & 3;

    const half *Ah, *Bh;
    int Mrows, pitch, kiter;
    if (MODE == 0) {
        Ah = g_Ah; Bh = g_Wv;
        Mrows = M_; pitch = E_; kiter = E_ / KBLK;
    } else if (MODE == 1) {
        const size_t ho = (size_t)blockIdx.z;
        Ah = g_Ph + ho * S_ * SP;
        Bh = g_Vh + ho * E_ * SP;
        Mrows = S_; pitch = SP; kiter = SP / KBLK;
    } else {
        Ah = g_Oh; Bh = g_Wo;
        Mrows = M_; pitch = E_; kiter = E_ / KBLK;
    }
    const int tm0 = blockIdx.y * 128, tn0 = blockIdx.x * 128;

    // 4 x 16B cp.async chunks per thread per stage (1024 chunks total)
    auto do_load = [&](int kt) {
        if (kt < kiter) {
            const uint32_t sbase = sb + (uint32_t)(kt % NSTAGE) * STAGE_BYTES;
            const int koff = kt * KBLK;
#pragma unroll
            for (int p = 0; p < 4; p++) {
                const int id  = p * 256 + tid;     // 0..1023
                const int row = id >> 3, c = id & 7;
                if (c < 4) {                       // A chunk
                    int grow = tm0 + row;
                    if (grow >= Mrows) grow = 0;   // clamp: never stored
                    cp16(sbase + swz(row, c),
                         Ah + (size_t)grow * pitch + koff + c * 8);
                } else {                           // B chunk (N=1024 exact)
                    cp16(sbase + swz(row, c),
                         Bh + (size_t)(tn0 + row) * pitch + koff + (c - 4) * 8);
                }
            }
        }
        CP_COMMIT();
    };

    float acc[4][4][4];
#pragma unroll
    for (int i = 0; i < 4; i++)
#pragma unroll
        for (int j = 0; j < 4; j++)
#pragma unroll
            for (int q = 0; q < 4; q++) acc[i][j][q] = 0.f;

    do_load(0); do_load(1); do_load(2);

    for (int kt = 0; kt < kiter; kt++) {
        CP_WAIT2();
        __syncthreads();
        const uint32_t Tb = sb + (uint32_t)(kt % NSTAGE) * STAGE_BYTES;

#pragma unroll
        for (int ks = 0; ks < 2; ks++) {
            uint32_t bf[4][2];
#pragma unroll
            for (int nt = 0; nt < 4; nt++) {
                const int nr = wn * 32 + nt * 8 + (lane & 7);
                const int c  = 4 + ks * 2 + ((lane >> 3) & 1);
                ldsm2(bf[nt], Tb + swz(nr, c));
            }
#pragma unroll
            for (int mt = 0; mt < 4; mt++) {
                uint32_t ah[4];
                {
                    const int mr = wm * 64 + mt * 16 + (lane & 15);
                    const int kh = lane >> 4;
                    ldsm4(ah, Tb + swz(mr, ks * 2 + kh));
                }
#pragma unroll
                for (int nt = 0; nt < 4; nt++)
                    mma_f16(acc[mt][nt], ah, bf[nt]);
            }
        }
        __syncthreads();
        do_load(kt + 3);
    }

    // ---------------- epilogue ----------------------------------------------
#pragma unroll
    for (int mt = 0; mt < 4; mt++) {
#pragma unroll
        for (int half_ = 0; half_ < 2; half_++) {
            const int m = tm0 + wm * 64 + mt * 16 + gid + half_ * 8;
            if (m >= Mrows) continue;
            int bb = 0, s = 0;
            if (MODE == 0) { bb = m / S_; s = m - bb * S_; }
#pragma unroll
            for (int nt = 0; nt < 4; nt++) {
                const int n0 = tn0 + wn * 32 + nt * 8 + tig * 2;
#pragma unroll
                for (int j = 0; j < 2; j++) {
                    const int n = n0 + j;
                    float v = acc[mt][nt][half_ * 2 + j];
                    if (MODE == 0) {
                        v += bias[n];
                        const size_t a = ((size_t)(n >> 6) * (B_ * D_)
                                          + (size_t)bb * D_ + (n & 63)) * SP + s;
                        g_Vh[a] = __float2half_rn(v);
                    } else if (MODE == 1) {
                        const size_t a = ((size_t)(n >> 6) * S_ + m) * E_
                                         + (size_t)blockIdx.z * D_ + (n & 63);
                        g_Oh[a] = __float2half_rn(v);
                    } else {
                        outp[(size_t)m * E_ + n] = v + bias[n];
                    }
                }
            }
        }
    }
}

// ---------------------------------------------------------------------------
// input conversions (fp32 -> fp16)
// ---------------------------------------------------------------------------
template <int W>
__global__ void cvt_fp16(const float* __restrict__ src, size_t n)
{
    half* d = (W == 0) ? g_Ah : (W == 1) ? g_Wv : g_Wo;
    const size_t stride = (size_t)gridDim.x * blockDim.x;
    for (size_t i = (size_t)blockIdx.x * blockDim.x + threadIdx.x; i < n; i += stride)
        d[i] = __float2half_rn(src[i]);
}

// ---------------------------------------------------------------------------
// softmax(share_bias) -> g_Ph (fp16), K padded to SP with zeros.
// Q path cancels: softmax is shift-invariant along the last axis.
// ---------------------------------------------------------------------------
__global__ __launch_bounds__(256)
void softmax_kernel(const float* __restrict__ bias)
{
    const int row = blockIdx.x;                     // h*S_ + i
    const float* __restrict__ src = bias + (size_t)row * S_;
    half* __restrict__ dh = g_Ph + (size_t)row * SP;
    const int tid = threadIdx.x;

    __shared__ float shm[8], shs[8];

    float v0 = (tid       < S_) ? src[tid]       : -3.0e38f;
    float v1 = (tid + 256 < S_) ? src[tid + 256] : -3.0e38f;
    float v2 = (tid + 512 < S_) ? src[tid + 512] : -3.0e38f;

    float mx = fmaxf(v0, fmaxf(v1, v2));
#pragma unroll
    for (int o = 16; o > 0; o >>= 1) mx = fmaxf(mx, __shfl_xor_sync(0xffffffffu, mx, o));
    if ((tid & 31) == 0) shm[tid >> 5] = mx;
    __syncthreads();
    mx = shm[0];
#pragma unroll
    for (int w = 1; w < 8; w++) mx = fmaxf(mx, shm[w]);

    float e0 = __expf(v0 - mx), e1 = __expf(v1 - mx), e2 = __expf(v2 - mx);
    float s = e0 + e1 + e2;
#pragma unroll
    for (int o = 16; o > 0; o >>= 1) s += __shfl_xor_sync(0xffffffffu, s, o);
    if ((tid & 31) == 0) shs[tid >> 5] = s;
    __syncthreads();
    s = shs[0];
#pragma unroll
    for (int w = 1; w < 8; w++) s += shs[w];
    const float inv = 1.0f / s;

#pragma unroll
    for (int q = 0; q < 3; q++) {
        const int c = tid + q * 256;
        if (c < SP) {
            const float pv = (c < S_) ? (q == 0 ? e0 : q == 1 ? e1 : e2) * inv : 0.f;
            dh[c] = __float2half_rn(pv);
        }
    }
}

// ---------------------------------------------------------------------------
extern "C" void kernel_launch(void* const* d_in, const int* in_sizes, int n_in,
                              void* d_out, int out_size)
{
    const float* hidden = (const float*)d_in[0];
    const float* v_w    = (const float*)d_in[3];
    const float* v_b    = (const float*)d_in[4];
    const float* out_w  = (const float*)d_in[5];
    const float* out_b  = (const float*)d_in[6];
    const float* s_bias = (const float*)d_in[8];
    float* out = (float*)d_out;

    cudaFuncSetAttribute(gemm_hmma<0>, cudaFuncAttributeMaxDynamicSharedMemorySize, SMEM_SZ);
    cudaFuncSetAttribute(gemm_hmma<1>, cudaFuncAttributeMaxDynamicSharedMemorySize, SMEM_SZ);
    cudaFuncSetAttribute(gemm_hmma<2>, cudaFuncAttributeMaxDynamicSharedMemorySize, SMEM_SZ);

    cvt_fp16<0><<<2048, 256>>>(hidden, (size_t)M_ * E_);
    cvt_fp16<1><<<512, 256>>>(v_w, (size_t)E_ * E_);
    cvt_fp16<2><<<512, 256>>>(out_w, (size_t)E_ * E_);
    softmax_kernel<<<H_ * S_, 256>>>(s_bias);

    gemm_hmma<0><<<dim3(8, 73),    256, SMEM_SZ>>>(v_b, nullptr);     // V projection
    gemm_hmma<1><<<dim3(8, 5, 16), 256, SMEM_SZ>>>(nullptr, nullptr); // P @ V
    gemm_hmma<2><<<dim3(8, 73),    256, SMEM_SZ>>>(out_b, out);       // out projection
}

// round 7
// speedup vs baseline: 9.1638x; 1.0729x over previous
#include <cuda_runtime.h>
#include <cuda_fp16.h>
#include <cstdint>

#define B_ 16
#define S_ 577
#define SP 640               // padded seq (K padding for GEMM2)
#define E_ 1024
#define H_ 16
#define D_ 64
#define M_ (B_ * S_)         // 9232

// ---------------- scratch (static device globals, zero-init at load) -------
__device__ half g_Ah[(size_t)M_ * E_];                   // hidden fp16
__device__ half g_Wv[(size_t)E_ * E_];                   // v_w fp16
__device__ half g_Wo[(size_t)E_ * E_];                   // out_w fp16
__device__ half g_Vh[(size_t)H_ * E_ * SP];              // V^T [h][(b,d)][s] (pad=0)
__device__ half g_Ph[(size_t)H_ * S_ * SP];              // softmax(P) (pad=0)
__device__ half g_Oh[(size_t)M_ * E_];                   // attn out fp16

// ---------------- PTX helpers (portable sm_80-level) ------------------------
__device__ __forceinline__ uint32_t smem_u32(const void* p) {
    uint32_t a;
    asm("{ .reg .u64 t; cvta.to.shared.u64 t, %1; cvt.u32.u64 %0, t; }" : "=r"(a) : "l"(p));
    return a;
}
__device__ __forceinline__ void cp16(uint32_t dst, const void* src) {
    asm volatile("cp.async.cg.shared.global [%0], [%1], 16;" :: "r"(dst), "l"(src));
}
#define CP_COMMIT() asm volatile("cp.async.commit_group;" ::: "memory")
#define CP_WAIT2()  asm volatile("cp.async.wait_group 2;" ::: "memory")

__device__ __forceinline__ void ldsm4(uint32_t* r, uint32_t addr) {
    asm volatile("ldmatrix.sync.aligned.m8n8.x4.shared.b16 {%0,%1,%2,%3}, [%4];"
                 : "=r"(r[0]), "=r"(r[1]), "=r"(r[2]), "=r"(r[3]) : "r"(addr));
}
__device__ __forceinline__ void ldsm2(uint32_t* r, uint32_t addr) {
    asm volatile("ldmatrix.sync.aligned.m8n8.x2.shared.b16 {%0,%1}, [%2];"
                 : "=r"(r[0]), "=r"(r[1]) : "r"(addr));
}
__device__ __forceinline__ void mma_f16(float* c, const uint32_t* a, const uint32_t* b) {
    asm volatile("mma.sync.aligned.m16n8k16.row.col.f32.f16.f16.f32 "
                 "{%0,%1,%2,%3}, {%4,%5,%6,%7}, {%8,%9}, {%0,%1,%2,%3};"
                 : "+f"(c[0]), "+f"(c[1]), "+f"(c[2]), "+f"(c[3])
                 : "r"(a[0]), "r"(a[1]), "r"(a[2]), "r"(a[3]), "r"(b[0]), "r"(b[1]));
}

// ---------------- tiling ----------------------------------------------------
// CTA tile 128x128, KBLK=64. Stage = A tile (128 rows x 128B = 64 halfs) +
// B tile (same). Row = 8 x 16B chunks, physical chunk = c ^ (row&7):
// ldmatrix's 8 row-addresses hit 8 distinct chunks -> conflict-free.
#define KBLK 64
#define NSTAGE 3
#define TILE_BYTES 16384
#define STAGE_BYTES (2 * TILE_BYTES)
#define SMEM_SZ (NSTAGE * STAGE_BYTES)       // 98304

__device__ __forceinline__ uint32_t swz(int row, int c) {
    return (uint32_t)(row * 128 + ((c ^ (row & 7)) << 4));
}

// ---------------------------------------------------------------------------
// fp16 HMMA GEMM, NT: C[m,n] = sum_k A[m,k]*B[n,k]
// MODE 0: V-proj   A=g_Ah, B=g_Wv, K=1024 -> g_Vh (V^T scatter, +v_b)
// MODE 1: P@V      A=g_Ph, B=g_Vh, K=640  -> g_Oh
// MODE 2: out-proj A=g_Oh, B=g_Wo, K=1024 -> d_out fp32 (+out_b)
// ---------------------------------------------------------------------------
template <int MODE>
__global__ __launch_bounds__(256, 2)
void gemm_hmma(const float* __restrict__ bias, float* __restrict__ outp)
{
    extern __shared__ __align__(1024) char smem[];
    const uint32_t sb = smem_u32(smem);
    const int tid  = threadIdx.x;
    const int wid  = tid >> 5, lane = tid & 31;
    const int wm   = wid & 1, wn = wid >> 1;      // warp grid 2m x 4n
    const int gid  = lane >> 2, tig = lane & 3;

    const half *Ah, *Bh;
    int Mrows, pitch, kiter;
    if (MODE == 0) {
        Ah = g_Ah; Bh = g_Wv;
        Mrows = M_; pitch = E_; kiter = E_ / KBLK;
    } else if (MODE == 1) {
        const size_t ho = (size_t)blockIdx.z;
        Ah = g_Ph + ho * S_ * SP;
        Bh = g_Vh + ho * E_ * SP;
        Mrows = S_; pitch = SP; kiter = SP / KBLK;
    } else {
        Ah = g_Oh; Bh = g_Wo;
        Mrows = M_; pitch = E_; kiter = E_ / KBLK;
    }
    const int tm0 = blockIdx.y * 128, tn0 = blockIdx.x * 128;

    // 8 x 16B cp.async chunks per thread per stage (A:1024 + B:1024 chunks)
    auto do_load = [&](int kt) {
        if (kt < kiter) {
            const uint32_t sbase = sb + (uint32_t)(kt % NSTAGE) * STAGE_BYTES;
            const int koff = kt * KBLK;
#pragma unroll
            for (int p = 0; p < 8; p++) {
                const int id   = p * 256 + tid;    // 0..2047
                const int tile = id >> 10;         // 0 = A, 1 = B
                const int rem  = id & 1023;
                const int row  = rem >> 3, c = rem & 7;
                if (tile == 0) {
                    int grow = tm0 + row;
                    if (grow >= Mrows) grow = 0;   // clamp: never stored
                    cp16(sbase + swz(row, c),
                         Ah + (size_t)grow * pitch + koff + c * 8);
                } else {                           // N = 1024 always exact
                    cp16(sbase + TILE_BYTES + swz(row, c),
                         Bh + (size_t)(tn0 + row) * pitch + koff + c * 8);
                }
            }
        }
        CP_COMMIT();
    };

    float acc[4][4][4];
#pragma unroll
    for (int i = 0; i < 4; i++)
#pragma unroll
        for (int j = 0; j < 4; j++)
#pragma unroll
            for (int q = 0; q < 4; q++) acc[i][j][q] = 0.f;

    do_load(0); do_load(1); do_load(2);

    for (int kt = 0; kt < kiter; kt++) {
        CP_WAIT2();
        __syncthreads();
        const uint32_t Ab = sb + (uint32_t)(kt % NSTAGE) * STAGE_BYTES;
        const uint32_t Bb = Ab + TILE_BYTES;

#pragma unroll
        for (int ks = 0; ks < 4; ks++) {           // 4 x k16 slices per k64
            uint32_t bf[4][2];
#pragma unroll
            for (int nt = 0; nt < 4; nt++) {
                const int nr = wn * 32 + nt * 8 + (lane & 7);
                const int c  = ks * 2 + ((lane >> 3) & 1);
                ldsm2(bf[nt], Bb + swz(nr, c));
            }
#pragma unroll
            for (int mt = 0; mt < 4; mt++) {
                uint32_t ah[4];
                {
                    const int mr = wm * 64 + mt * 16 + (lane & 15);
                    const int kh = lane >> 4;
                    ldsm4(ah, Ab + swz(mr, ks * 2 + kh));
                }
#pragma unroll
                for (int nt = 0; nt < 4; nt++)
                    mma_f16(acc[mt][nt], ah, bf[nt]);
            }
        }
        __syncthreads();
        do_load(kt + 3);
    }

    // ---------------- epilogue ----------------------------------------------
#pragma unroll
    for (int mt = 0; mt < 4; mt++) {
#pragma unroll
        for (int half_ = 0; half_ < 2; half_++) {
            const int m = tm0 + wm * 64 + mt * 16 + gid + half_ * 8;
            if (m >= Mrows) continue;
            int bb = 0, s = 0;
            if (MODE == 0) { bb = m / S_; s = m - bb * S_; }
#pragma unroll
            for (int nt = 0; nt < 4; nt++) {
                const int n0 = tn0 + wn * 32 + nt * 8 + tig * 2;
#pragma unroll
                for (int j = 0; j < 2; j++) {
                    const int n = n0 + j;
                    float v = acc[mt][nt][half_ * 2 + j];
                    if (MODE == 0) {
                        v += bias[n];
                        const size_t a = ((size_t)(n >> 6) * (B_ * D_)
                                          + (size_t)bb * D_ + (n & 63)) * SP + s;
                        g_Vh[a] = __float2half_rn(v);
                    } else if (MODE == 1) {
                        const size_t a = ((size_t)(n >> 6) * S_ + m) * E_
                                         + (size_t)blockIdx.z * D_ + (n & 63);
                        g_Oh[a] = __float2half_rn(v);
                    } else {
                        outp[(size_t)m * E_ + n] = v + bias[n];
                    }
                }
            }
        }
    }
}

// ---------------------------------------------------------------------------
// single fused conversion kernel: hidden -> g_Ah, v_w -> g_Wv, out_w -> g_Wo
// ---------------------------------------------------------------------------
__global__ void cvt_all(const float* __restrict__ hid,
                        const float* __restrict__ vw,
                        const float* __restrict__ ow)
{
    const size_t NH = (size_t)M_ * E_;
    const size_t NW = (size_t)E_ * E_;
    const size_t total = NH + 2 * NW;
    const size_t stride = (size_t)gridDim.x * blockDim.x;
    for (size_t i = (size_t)blockIdx.x * blockDim.x + threadIdx.x; i < total; i += stride) {
        if (i < NH)            g_Ah[i]           = __float2half_rn(hid[i]);
        else if (i < NH + NW)  g_Wv[i - NH]      = __float2half_rn(vw[i - NH]);
        else                   g_Wo[i - NH - NW] = __float2half_rn(ow[i - NH - NW]);
    }
}

// ---------------------------------------------------------------------------
// softmax(share_bias) -> g_Ph (fp16), K padded to SP with zeros.
// Q path cancels: softmax is shift-invariant along the last axis.
// ---------------------------------------------------------------------------
__global__ __launch_bounds__(256)
void softmax_kernel(const float* __restrict__ bias)
{
    const int row = blockIdx.x;                     // h*S_ + i
    const float* __restrict__ src = bias + (size_t)row * S_;
    half* __restrict__ dh = g_Ph + (size_t)row * SP;
    const int tid = threadIdx.x;

    __shared__ float shm[8], shs[8];

    float v0 = (tid       < S_) ? src[tid]       : -3.0e38f;
    float v1 = (tid + 256 < S_) ? src[tid + 256] : -3.0e38f;
    float v2 = (tid + 512 < S_) ? src[tid + 512] : -3.0e38f;

    float mx = fmaxf(v0, fmaxf(v1, v2));
#pragma unroll
    for (int o = 16; o > 0; o >>= 1) mx = fmaxf(mx, __shfl_xor_sync(0xffffffffu, mx, o));
    if ((tid & 31) == 0) shm[tid >> 5] = mx;
    __syncthreads();
    mx = shm[0];
#pragma unroll
    for (int w = 1; w < 8; w++) mx = fmaxf(mx, shm[w]);

    float e0 = __expf(v0 - mx), e1 = __expf(v1 - mx), e2 = __expf(v2 - mx);
    float s = e0 + e1 + e2;
#pragma unroll
    for (int o = 16; o > 0; o >>= 1) s += __shfl_xor_sync(0xffffffffu, s, o);
    if ((tid & 31) == 0) shs[tid >> 5] = s;
    __syncthreads();
    s = shs[0];
#pragma unroll
    for (int w = 1; w < 8; w++) s += shs[w];
    const float inv = 1.0f / s;

#pragma unroll
    for (int q = 0; q < 3; q++) {
        const int c = tid + q * 256;
        if (c < SP) {
            const float pv = (c < S_) ? (q == 0 ? e0 : q == 1 ? e1 : e2) * inv : 0.f;
            dh[c] = __float2half_rn(pv);
        }
    }
}

// ---------------------------------------------------------------------------
extern "C" void kernel_launch(void* const* d_in, const int* in_sizes, int n_in,
                              void* d_out, int out_size)
{
    const float* hidden = (const float*)d_in[0];
    const float* v_w    = (const float*)d_in[3];
    const float* v_b    = (const float*)d_in[4];
    const float* out_w  = (const float*)d_in[5];
    const float* out_b  = (const float*)d_in[6];
    const float* s_bias = (const float*)d_in[8];
    float* out = (float*)d_out;

    cudaFuncSetAttribute(gemm_hmma<0>, cudaFuncAttributeMaxDynamicSharedMemorySize, SMEM_SZ);
    cudaFuncSetAttribute(gemm_hmma<1>, cudaFuncAttributeMaxDynamicSharedMemorySize, SMEM_SZ);
    cudaFuncSetAttribute(gemm_hmma<2>, cudaFuncAttributeMaxDynamicSharedMemorySize, SMEM_SZ);

    cvt_all<<<2960, 256>>>(hidden, v_w, out_w);
    softmax_kernel<<<H_ * S_, 256>>>(s_bias);

    gemm_hmma<0><<<dim3(8, 73),    256, SMEM_SZ>>>(v_b, nullptr);     // V projection
    gemm_hmma<1><<<dim3(8, 5, 16), 256, SMEM_SZ>>>(nullptr, nullptr); // P @ V
    gemm_hmma<2><<<dim3(8, 73),    256, SMEM_SZ>>>(out_b, out);       // out projection
}

// round 8
// speedup vs baseline: 9.5801x; 1.0454x over previous
#include <cuda_runtime.h>
#include <cuda_fp16.h>
#include <cstdint>

#define B_ 16
#define S_ 577
#define SP 640               // padded seq (K padding for GEMM2)
#define E_ 1024
#define H_ 16
#define D_ 64
#define M_ (B_ * S_)         // 9232

// ---------------- scratch (static device globals, zero-init at load) -------
__device__ half g_Ah[(size_t)M_ * E_];                   // hidden fp16
__device__ half g_Wv[(size_t)E_ * E_];                   // v_w fp16
__device__ half g_Wo[(size_t)E_ * E_];                   // out_w fp16
__device__ half g_Vh[(size_t)H_ * E_ * SP];              // V^T [h][(b,d)][s] (pad=0)
__device__ half g_Ph[(size_t)H_ * S_ * SP];              // softmax(P) (pad=0)
__device__ half g_Oh[(size_t)M_ * E_];                   // attn out fp16

// ---------------- PTX helpers (portable sm_80-level) ------------------------
__device__ __forceinline__ uint32_t smem_u32(const void* p) {
    uint32_t a;
    asm("{ .reg .u64 t; cvta.to.shared.u64 t, %1; cvt.u32.u64 %0, t; }" : "=r"(a) : "l"(p));
    return a;
}
__device__ __forceinline__ void cp16(uint32_t dst, const void* src) {
    asm volatile("cp.async.cg.shared.global [%0], [%1], 16;" :: "r"(dst), "l"(src));
}
#define CP_COMMIT() asm volatile("cp.async.commit_group;" ::: "memory")
#define CP_WAIT2()  asm volatile("cp.async.wait_group 2;" ::: "memory")

__device__ __forceinline__ void ldsm4(uint32_t* r, uint32_t addr) {
    asm volatile("ldmatrix.sync.aligned.m8n8.x4.shared.b16 {%0,%1,%2,%3}, [%4];"
                 : "=r"(r[0]), "=r"(r[1]), "=r"(r[2]), "=r"(r[3]) : "r"(addr));
}
__device__ __forceinline__ void ldsm2(uint32_t* r, uint32_t addr) {
    asm volatile("ldmatrix.sync.aligned.m8n8.x2.shared.b16 {%0,%1}, [%2];"
                 : "=r"(r[0]), "=r"(r[1]) : "r"(addr));
}
__device__ __forceinline__ void mma_f16(float* c, const uint32_t* a, const uint32_t* b) {
    asm volatile("mma.sync.aligned.m16n8k16.row.col.f32.f16.f16.f32 "
                 "{%0,%1,%2,%3}, {%4,%5,%6,%7}, {%8,%9}, {%0,%1,%2,%3};"
                 : "+f"(c[0]), "+f"(c[1]), "+f"(c[2]), "+f"(c[3])
                 : "r"(a[0]), "r"(a[1]), "r"(a[2]), "r"(a[3]), "r"(b[0]), "r"(b[1]));
}

// ---------------- tiling ----------------------------------------------------
// KBLK=64. Row = 8 x 16B chunks, physical chunk = c ^ (row&7): ldmatrix's
// 8 row-addresses hit 8 distinct chunks -> conflict-free.
// MODE 0/2: CTA 128x128 (2 CTA/SM, 1.97-wave grids — already well packed).
// MODE 1:   CTA  64x128 (3 CTA/SM -> 444 concurrent; 1280 CTAs = 2.88 waves
//           -> 96% packing vs 72% at 128x128).
#define KBLK 64
#define NSTAGE 3
#define B_TILE_BYTES 16384

__device__ __forceinline__ uint32_t swz(int row, int c) {
    return (uint32_t)(row * 128 + ((c ^ (row & 7)) << 4));
}

template <int MODE> struct Cfg {
    static constexpr int BM = (MODE == 1) ? 64 : 128;
    static constexpr int MT = BM / 32;                       // m16 frags per warp
    static constexpr int A_BYTES = BM * 128;
    static constexpr int STAGE = A_BYTES + B_TILE_BYTES;
    static constexpr int SMEM = NSTAGE * STAGE;              // 98304 / 73728
    static constexpr int NCHUNK = (BM * 8 + 1024) / 256;     // per-thread cp16s
    static constexpr int OCC = (MODE == 1) ? 3 : 2;
};

// ---------------------------------------------------------------------------
// fp16 HMMA GEMM, NT: C[m,n] = sum_k A[m,k]*B[n,k]
// MODE 0: V-proj   A=g_Ah, B=g_Wv, K=1024 -> g_Vh (V^T scatter, +v_b)
// MODE 1: P@V      A=g_Ph, B=g_Vh, K=640  -> g_Oh
// MODE 2: out-proj A=g_Oh, B=g_Wo, K=1024 -> d_out fp32 (+out_b)
// ---------------------------------------------------------------------------
template <int MODE>
__global__ __launch_bounds__(256, Cfg<MODE>::OCC)
void gemm_hmma(const float* __restrict__ bias, float* __restrict__ outp)
{
    using C = Cfg<MODE>;
    extern __shared__ __align__(1024) char smem[];
    const uint32_t sb = smem_u32(smem);
    const int tid  = threadIdx.x;
    const int wid  = tid >> 5, lane = tid & 31;
    const int wm   = wid & 1, wn = wid >> 1;      // warp grid 2m x 4n
    const int gid  = lane >> 2, tig = lane & 3;
    constexpr int WM_ROWS = C::BM / 2;            // rows per m-warp

    const half *Ah, *Bh;
    int Mrows, pitch, kiter;
    if (MODE == 0) {
        Ah = g_Ah; Bh = g_Wv;
        Mrows = M_; pitch = E_; kiter = E_ / KBLK;
    } else if (MODE == 1) {
        const size_t ho = (size_t)blockIdx.z;
        Ah = g_Ph + ho * S_ * SP;
        Bh = g_Vh + ho * E_ * SP;
        Mrows = S_; pitch = SP; kiter = SP / KBLK;
    } else {
        Ah = g_Oh; Bh = g_Wo;
        Mrows = M_; pitch = E_; kiter = E_ / KBLK;
    }
    const int tm0 = blockIdx.y * C::BM, tn0 = blockIdx.x * 128;

    auto do_load = [&](int kt) {
        if (kt < kiter) {
            const uint32_t sbase = sb + (uint32_t)(kt % NSTAGE) * C::STAGE;
            const int koff = kt * KBLK;
#pragma unroll
            for (int p = 0; p < C::NCHUNK; p++) {
                const int id = p * 256 + tid;
                if (id < C::BM * 8) {              // A chunk
                    const int row = id >> 3, c = id & 7;
                    int grow = tm0 + row;
                    if (grow >= Mrows) grow = 0;   // clamp: never stored
                    cp16(sbase + swz(row, c),
                         Ah + (size_t)grow * pitch + koff + c * 8);
                } else {                           // B chunk (N=1024 exact)
                    const int idb = id - C::BM * 8;
                    const int row = idb >> 3, c = idb & 7;
                    cp16(sbase + (uint32_t)C::A_BYTES + swz(row, c),
                         Bh + (size_t)(tn0 + row) * pitch + koff + c * 8);
                }
            }
        }
        CP_COMMIT();
    };

    float acc[C::MT][4][4];
#pragma unroll
    for (int i = 0; i < C::MT; i++)
#pragma unroll
        for (int j = 0; j < 4; j++)
#pragma unroll
            for (int q = 0; q < 4; q++) acc[i][j][q] = 0.f;

    do_load(0); do_load(1); do_load(2);

    for (int kt = 0; kt < kiter; kt++) {
        CP_WAIT2();
        __syncthreads();
        const uint32_t Ab = sb + (uint32_t)(kt % NSTAGE) * C::STAGE;
        const uint32_t Bb = Ab + C::A_BYTES;

#pragma unroll
        for (int ks = 0; ks < 4; ks++) {           // 4 x k16 slices per k64
            uint32_t bf[4][2];
#pragma unroll
            for (int nt = 0; nt < 4; nt++) {
                const int nr = wn * 32 + nt * 8 + (lane & 7);
                const int c  = ks * 2 + ((lane >> 3) & 1);
                ldsm2(bf[nt], Bb + swz(nr, c));
            }
#pragma unroll
            for (int mt = 0; mt < C::MT; mt++) {
                uint32_t ah[4];
                {
                    const int mr = wm * WM_ROWS + mt * 16 + (lane & 15);
                    const int kh = lane >> 4;
                    ldsm4(ah, Ab + swz(mr, ks * 2 + kh));
                }
#pragma unroll
                for (int nt = 0; nt < 4; nt++)
                    mma_f16(acc[mt][nt], ah, bf[nt]);
            }
        }
        __syncthreads();
        do_load(kt + 3);
    }

    // ---------------- epilogue ----------------------------------------------
#pragma unroll
    for (int mt = 0; mt < C::MT; mt++) {
#pragma unroll
        for (int half_ = 0; half_ < 2; half_++) {
            const int m = tm0 + wm * WM_ROWS + mt * 16 + gid + half_ * 8;
            if (m >= Mrows) continue;
            int bb = 0, s = 0;
            if (MODE == 0) { bb = m / S_; s = m - bb * S_; }
#pragma unroll
            for (int nt = 0; nt < 4; nt++) {
                const int n0 = tn0 + wn * 32 + nt * 8 + tig * 2;
#pragma unroll
                for (int j = 0; j < 2; j++) {
                    const int n = n0 + j;
                    float v = acc[mt][nt][half_ * 2 + j];
                    if (MODE == 0) {
                        v += bias[n];
                        const size_t a = ((size_t)(n >> 6) * (B_ * D_)
                                          + (size_t)bb * D_ + (n & 63)) * SP + s;
                        g_Vh[a] = __float2half_rn(v);
                    } else if (MODE == 1) {
                        const size_t a = ((size_t)(n >> 6) * S_ + m) * E_
                                         + (size_t)blockIdx.z * D_ + (n & 63);
                        g_Oh[a] = __float2half_rn(v);
                    } else {
                        outp[(size_t)m * E_ + n] = v + bias[n];
                    }
                }
            }
        }
    }
}

// ---------------------------------------------------------------------------
// Fused preamble: blocks [0, H*S) do softmax rows -> g_Ph; the rest do
// grid-stride fp32->fp16 conversion (hidden, v_w, out_w). Independent work
// in one launch so both run concurrently across the chip.
// Q path cancels: softmax is shift-invariant along the last axis.
// ---------------------------------------------------------------------------
#define CVT_BLOCKS 2960
__global__ __launch_bounds__(256)
void preamble(const float* __restrict__ sbias,
              const float* __restrict__ hid,
              const float* __restrict__ vw,
              const float* __restrict__ ow)
{
    const int tid = threadIdx.x;
    if (blockIdx.x < H_ * S_) {
        // ---- softmax row ----
        const int row = blockIdx.x;
        const float* __restrict__ src = sbias + (size_t)row * S_;
        half* __restrict__ dh = g_Ph + (size_t)row * SP;

        __shared__ float shm[8], shs[8];

        float v0 = (tid       < S_) ? src[tid]       : -3.0e38f;
        float v1 = (tid + 256 < S_) ? src[tid + 256] : -3.0e38f;
        float v2 = (tid + 512 < S_) ? src[tid + 512] : -3.0e38f;

        float mx = fmaxf(v0, fmaxf(v1, v2));
#pragma unroll
        for (int o = 16; o > 0; o >>= 1) mx = fmaxf(mx, __shfl_xor_sync(0xffffffffu, mx, o));
        if ((tid & 31) == 0) shm[tid >> 5] = mx;
        __syncthreads();
        mx = shm[0];
#pragma unroll
        for (int w = 1; w < 8; w++) mx = fmaxf(mx, shm[w]);

        float e0 = __expf(v0 - mx), e1 = __expf(v1 - mx), e2 = __expf(v2 - mx);
        float s = e0 + e1 + e2;
#pragma unroll
        for (int o = 16; o > 0; o >>= 1) s += __shfl_xor_sync(0xffffffffu, s, o);
        if ((tid & 31) == 0) shs[tid >> 5] = s;
        __syncthreads();
        s = shs[0];
#pragma unroll
        for (int w = 1; w < 8; w++) s += shs[w];
        const float inv = 1.0f / s;

#pragma unroll
        for (int q = 0; q < 3; q++) {
            const int c = tid + q * 256;
            if (c < SP) {
                const float pv = (c < S_) ? (q == 0 ? e0 : q == 1 ? e1 : e2) * inv : 0.f;
                dh[c] = __float2half_rn(pv);
            }
        }
    } else {
        // ---- fp32 -> fp16 conversions ----
        const size_t NH = (size_t)M_ * E_;
        const size_t NW = (size_t)E_ * E_;
        const size_t total = NH + 2 * NW;
        const size_t stride = (size_t)CVT_BLOCKS * 256;
        size_t i = (size_t)(blockIdx.x - H_ * S_) * 256 + tid;
        for (; i < total; i += stride) {
            if (i < NH)            g_Ah[i]           = __float2half_rn(hid[i]);
            else if (i < NH + NW)  g_Wv[i - NH]      = __float2half_rn(vw[i - NH]);
            else                   g_Wo[i - NH - NW] = __float2half_rn(ow[i - NH - NW]);
        }
    }
}

// ---------------------------------------------------------------------------
extern "C" void kernel_launch(void* const* d_in, const int* in_sizes, int n_in,
                              void* d_out, int out_size)
{
    const float* hidden = (const float*)d_in[0];
    const float* v_w    = (const float*)d_in[3];
    const float* v_b    = (const float*)d_in[4];
    const float* out_w  = (const float*)d_in[5];
    const float* out_b  = (const float*)d_in[6];
    const float* s_bias = (const float*)d_in[8];
    float* out = (float*)d_out;

    cudaFuncSetAttribute(gemm_hmma<0>, cudaFuncAttributeMaxDynamicSharedMemorySize, Cfg<0>::SMEM);
    cudaFuncSetAttribute(gemm_hmma<1>, cudaFuncAttributeMaxDynamicSharedMemorySize, Cfg<1>::SMEM);
    cudaFuncSetAttribute(gemm_hmma<2>, cudaFuncAttributeMaxDynamicSharedMemorySize, Cfg<2>::SMEM);

    preamble<<<H_ * S_ + CVT_BLOCKS, 256>>>(s_bias, hidden, v_w, out_w);

    gemm_hmma<0><<<dim3(8, 73),     256, Cfg<0>::SMEM>>>(v_b, nullptr);     // V proj
    gemm_hmma<1><<<dim3(8, 10, 16), 256, Cfg<1>::SMEM>>>(nullptr, nullptr); // P @ V
    gemm_hmma<2><<<dim3(8, 73),     256, Cfg<2>::SMEM>>>(out_b, out);       // out proj
}